// round 1
// baseline (speedup 1.0000x reference)
#include <cuda_runtime.h>
#include <cstdint>

#define S_GRID   1024
#define NPTS     (S_GRID * S_GRID)
#define NLEV     16
#define TBL      (1u << 19)
#define TMASK    (TBL - 1u)
#define ENC_DIM  32
#define HID      64
#define OUTC     3
#define PRIME_Y  2654435761u
#define TPB      256

// resolutions = floor(16 * 1.5^l) computed in fp32 (exact: 3^l/2^l mantissas < 2^24)
__device__ __constant__ int c_res[NLEV] =
    {16, 24, 36, 54, 81, 121, 182, 273, 410, 615,
     922, 1383, 2075, 3113, 4670, 7006};
// (res+1)^2 <= 2^19  ->  res <= 723  -> levels 0..9 dense, 10..15 hashed

// ---------------- f32x2 packed math helpers ----------------
__device__ __forceinline__ unsigned long long pack2(float x, float y) {
    unsigned long long r;
    asm("mov.b64 %0, {%1, %2};" : "=l"(r) : "f"(x), "f"(y));
    return r;
}
__device__ __forceinline__ void unpack2(unsigned long long v, float& x, float& y) {
    asm("mov.b64 {%0, %1}, %2;" : "=f"(x), "=f"(y) : "l"(v));
}
__device__ __forceinline__ unsigned long long fma2(unsigned long long a,
                                                   unsigned long long b,
                                                   unsigned long long c) {
    unsigned long long d;
    asm("fma.rn.f32x2 %0, %1, %2, %3;" : "=l"(d) : "l"(a), "l"(b), "l"(c));
    return d;
}

// smem layout (floats): W0[2048] | W1[4096] | W2[192] | act[64*256]
#define SM_W0   0
#define SM_W1   2048
#define SM_W2   (2048 + 4096)
#define SM_ACT  (2048 + 4096 + 192)
#define SMEM_FLOATS (SM_ACT + HID * TPB)
#define SMEM_BYTES  (SMEM_FLOATS * 4)

__global__ __launch_bounds__(TPB, 2)
void ngp_fused_kernel(const float* __restrict__ xy,
                      const float* __restrict__ tables,
                      const float* __restrict__ gW0,
                      const float* __restrict__ gW1,
                      const float* __restrict__ gW2,
                      float* __restrict__ out)
{
    extern __shared__ float smem[];
    float* sW0 = smem + SM_W0;
    float* sW1 = smem + SM_W1;
    float* sW2 = smem + SM_W2;
    float* act = smem + SM_ACT + threadIdx.x;   // column layout: act[k*TPB]

    // ---- stage weights in shared ----
    for (int i = threadIdx.x; i < ENC_DIM * HID; i += TPB) sW0[i] = gW0[i];
    for (int i = threadIdx.x; i < HID * HID;     i += TPB) sW1[i] = gW1[i];
    if (threadIdx.x < HID * OUTC) sW2[threadIdx.x] = gW2[threadIdx.x];
    __syncthreads();

    const int p = blockIdx.x * TPB + threadIdx.x;
    const float x0 = xy[2 * p];
    const float x1 = xy[2 * p + 1];

    // ---------------- hash-grid encoding ----------------
#pragma unroll
    for (int l = 0; l < NLEV; ++l) {
        const int   res  = c_res[l];
        const float resf = (float)res;
        const float pos0 = x0 * resf;
        const float pos1 = x1 * resf;
        const float f0 = floorf(pos0);
        const float f1 = floorf(pos1);
        const int   i0 = (int)f0;
        const int   i1 = (int)f1;
        const float w0 = pos0 - f0;
        const float w1 = pos1 - f1;

        int idx00, idx01, idx10, idx11;
        if (l < 10) {                 // dense: idx = c0 + c1*(res+1)
            const int r1   = res + 1;
            const int base = i0 + i1 * r1;
            idx00 = base;         // (0,0)
            idx01 = base + r1;    // (0,1)
            idx10 = base + 1;     // (1,0)
            idx11 = base + r1 + 1;// (1,1)
        } else {                      // hash: (c0 ^ c1*PRIME) & TMASK
            const unsigned u0 = (unsigned)i0;
            const unsigned u1 = (unsigned)i1;
            const unsigned h0 = u1 * PRIME_Y;
            const unsigned h1 = (u1 + 1u) * PRIME_Y;
            idx00 = (int)((u0        ^ h0) & TMASK);
            idx01 = (int)((u0        ^ h1) & TMASK);
            idx10 = (int)(((u0 + 1u) ^ h0) & TMASK);
            idx11 = (int)(((u0 + 1u) ^ h1) & TMASK);
        }

        const float2* tab = (const float2*)(tables) + (size_t)l * TBL;
        const float2 v00 = __ldg(tab + idx00);
        const float2 v01 = __ldg(tab + idx01);
        const float2 v10 = __ldg(tab + idx10);
        const float2 v11 = __ldg(tab + idx11);

        const float a0 = 1.f - w0;
        const float a1 = 1.f - w1;
        const float wt00 = a0 * a1;
        const float wt01 = a0 * w1;
        const float wt10 = w0 * a1;
        const float wt11 = w0 * w1;

        const float e0 = v00.x * wt00 + v01.x * wt01 + v10.x * wt10 + v11.x * wt11;
        const float e1 = v00.y * wt00 + v01.y * wt01 + v10.y * wt10 + v11.y * wt11;

        act[(2 * l)     * TPB] = e0;
        act[(2 * l + 1) * TPB] = e1;
    }

    // ---------------- layer 0: enc(32) @ W0(32x64), relu ----------------
    unsigned long long h1[HID / 2];
#pragma unroll
    for (int j = 0; j < HID / 2; ++j) h1[j] = 0ull;

#pragma unroll 2
    for (int k = 0; k < ENC_DIM; ++k) {
        const float a = act[k * TPB];
        const unsigned long long bc = pack2(a, a);
        const ulonglong2* wr = (const ulonglong2*)(sW0 + k * HID);
#pragma unroll
        for (int j = 0; j < HID / 4; ++j) {
            const ulonglong2 w = wr[j];
            h1[2 * j]     = fma2(bc, w.x, h1[2 * j]);
            h1[2 * j + 1] = fma2(bc, w.y, h1[2 * j + 1]);
        }
    }
    // relu -> back to act columns
#pragma unroll
    for (int j = 0; j < HID / 2; ++j) {
        float a, b;
        unpack2(h1[j], a, b);
        act[(2 * j)     * TPB] = fmaxf(a, 0.f);
        act[(2 * j + 1) * TPB] = fmaxf(b, 0.f);
    }

    // ---------------- layer 1: h(64) @ W1(64x64), relu ----------------
    unsigned long long h2[HID / 2];
#pragma unroll
    for (int j = 0; j < HID / 2; ++j) h2[j] = 0ull;

#pragma unroll 2
    for (int k = 0; k < HID; ++k) {
        const float a = act[k * TPB];
        const unsigned long long bc = pack2(a, a);
        const ulonglong2* wr = (const ulonglong2*)(sW1 + k * HID);
#pragma unroll
        for (int j = 0; j < HID / 4; ++j) {
            const ulonglong2 w = wr[j];
            h2[2 * j]     = fma2(bc, w.x, h2[2 * j]);
            h2[2 * j + 1] = fma2(bc, w.y, h2[2 * j + 1]);
        }
    }

    // ---------------- layer 2: h(64) @ W2(64x3) ----------------
    float o0 = 0.f, o1 = 0.f, o2 = 0.f;
#pragma unroll
    for (int j = 0; j < HID / 2; ++j) {
        float a, b;
        unpack2(h2[j], a, b);
        a = fmaxf(a, 0.f);
        b = fmaxf(b, 0.f);
        const int ka = 2 * j, kb = 2 * j + 1;
        o0 += a * sW2[ka * 3 + 0] + b * sW2[kb * 3 + 0];
        o1 += a * sW2[ka * 3 + 1] + b * sW2[kb * 3 + 1];
        o2 += a * sW2[ka * 3 + 2] + b * sW2[kb * 3 + 2];
    }

    out[p]             = o0;
    out[NPTS + p]      = o1;
    out[2 * NPTS + p]  = o2;
}

extern "C" void kernel_launch(void* const* d_in, const int* in_sizes, int n_in,
                              void* d_out, int out_size)
{
    const float* xy  = nullptr;
    const float* tab = nullptr;
    const float* W0  = nullptr;
    const float* W1  = nullptr;
    const float* W2  = nullptr;

    for (int i = 0; i < n_in; ++i) {
        switch (in_sizes[i]) {
            case 2 * NPTS:                 xy  = (const float*)d_in[i]; break; // 2097152
            case (int)(NLEV * TBL * 2):    tab = (const float*)d_in[i]; break; // 16777216
            case ENC_DIM * HID:            W0  = (const float*)d_in[i]; break; // 2048
            case HID * HID:                W1  = (const float*)d_in[i]; break; // 4096
            case HID * OUTC:               W2  = (const float*)d_in[i]; break; // 192
            default: break;
        }
    }

    cudaFuncSetAttribute(ngp_fused_kernel,
                         cudaFuncAttributeMaxDynamicSharedMemorySize, SMEM_BYTES);

    ngp_fused_kernel<<<NPTS / TPB, TPB, SMEM_BYTES>>>(
        xy, tab, W0, W1, W2, (float*)d_out);
}

// round 4
// speedup vs baseline: 1.5847x; 1.5847x over previous
#include <cuda_runtime.h>
#include <cstdint>

#define S_GRID   1024
#define NPTS     (S_GRID * S_GRID)
#define NLEV     16
#define TBL      (1u << 19)
#define TMASK    (TBL - 1u)
#define ENC_DIM  32
#define HID      64
#define OUTC     3
#define PRIME_Y  2654435761u
#define TPB      128
#define PPT      2          // points per thread

__device__ __constant__ int c_res[NLEV] =
    {16, 24, 36, 54, 81, 121, 182, 273, 410, 615,
     922, 1383, 2075, 3113, 4670, 7006};
// levels 0..9 dense ((res+1)^2 <= 2^19), 10..15 hashed

// ---------------- f32x2 packed math helpers ----------------
__device__ __forceinline__ unsigned long long pack2(float x, float y) {
    unsigned long long r;
    asm("mov.b64 %0, {%1, %2};" : "=l"(r) : "f"(x), "f"(y));
    return r;
}
__device__ __forceinline__ void unpack2(unsigned long long v, float& x, float& y) {
    asm("mov.b64 {%0, %1}, %2;" : "=f"(x), "=f"(y) : "l"(v));
}
__device__ __forceinline__ unsigned long long fma2(unsigned long long a,
                                                   unsigned long long b,
                                                   unsigned long long c) {
    unsigned long long d;
    asm("fma.rn.f32x2 %0, %1, %2, %3;" : "=l"(d) : "l"(a), "l"(b), "l"(c));
    return d;
}

// smem (floats): W0[2048] | W1[4096] | W2[192] | act pairs float2[64][TPB]
#define SM_W0   0
#define SM_W1   2048
#define SM_W2   (2048 + 4096)
#define SM_ACT  (2048 + 4096 + 192)                 // 6336 floats, 8B-aligned
#define SMEM_FLOATS (SM_ACT + HID * TPB * 2)
#define SMEM_BYTES  (SMEM_FLOATS * 4)

__global__ __launch_bounds__(TPB, 2)
void ngp_fused_kernel(const float* __restrict__ xy,
                      const float* __restrict__ tables,
                      const float* __restrict__ gW0,
                      const float* __restrict__ gW1,
                      const float* __restrict__ gW2,
                      float* __restrict__ out)
{
    extern __shared__ float smem[];
    float* sW0 = smem + SM_W0;
    float* sW1 = smem + SM_W1;
    float* sW2 = smem + SM_W2;
    float2* actp = (float2*)(smem + SM_ACT) + threadIdx.x;  // actp[k*TPB]

    // ---- stage weights in shared (vectorized) ----
    {
        const float4* s0 = (const float4*)gW0;
        const float4* s1 = (const float4*)gW1;
        float4* d0 = (float4*)sW0;
        float4* d1 = (float4*)sW1;
        for (int i = threadIdx.x; i < (ENC_DIM * HID) / 4; i += TPB) d0[i] = s0[i];
        for (int i = threadIdx.x; i < (HID * HID) / 4;    i += TPB) d1[i] = s1[i];
        if (threadIdx.x < HID * OUTC / 2)
            ((float2*)sW2)[threadIdx.x] = ((const float2*)gW2)[threadIdx.x];
    }
    __syncthreads();

    const int t  = blockIdx.x * TPB + threadIdx.x;
    // points 2t and 2t+1 (adjacent in x -> good gather locality)
    const float4 xyv = ((const float4*)xy)[t];
    const float px[PPT] = {xyv.x, xyv.z};
    const float py[PPT] = {xyv.y, xyv.w};

    // ---------------- hash-grid encoding (both points) ----------------
#pragma unroll
    for (int l = 0; l < NLEV; ++l) {
        const int   res  = c_res[l];
        const float resf = (float)res;
        const float2* tab = (const float2*)(tables) + (size_t)l * TBL;
        float e0[PPT], e1[PPT];
#pragma unroll
        for (int q = 0; q < PPT; ++q) {
            const float pos0 = px[q] * resf;
            const float pos1 = py[q] * resf;
            const float f0 = floorf(pos0);
            const float f1 = floorf(pos1);
            const int   i0 = (int)f0;
            const int   i1 = (int)f1;
            const float w0 = pos0 - f0;
            const float w1 = pos1 - f1;

            int idx00, idx01, idx10, idx11;
            if (l < 10) {                 // dense
                const int r1   = res + 1;
                const int base = i0 + i1 * r1;
                idx00 = base;
                idx01 = base + r1;
                idx10 = base + 1;
                idx11 = base + r1 + 1;
            } else {                      // hashed
                const unsigned u0 = (unsigned)i0;
                const unsigned u1 = (unsigned)i1;
                const unsigned h0 = u1 * PRIME_Y;
                const unsigned h1 = (u1 + 1u) * PRIME_Y;
                idx00 = (int)((u0        ^ h0) & TMASK);
                idx01 = (int)((u0        ^ h1) & TMASK);
                idx10 = (int)(((u0 + 1u) ^ h0) & TMASK);
                idx11 = (int)(((u0 + 1u) ^ h1) & TMASK);
            }

            const float2 v00 = __ldg(tab + idx00);
            const float2 v01 = __ldg(tab + idx01);
            const float2 v10 = __ldg(tab + idx10);
            const float2 v11 = __ldg(tab + idx11);

            const float a0 = 1.f - w0;
            const float a1 = 1.f - w1;
            const float wt00 = a0 * a1;
            const float wt01 = a0 * w1;
            const float wt10 = w0 * a1;
            const float wt11 = w0 * w1;

            e0[q] = v00.x * wt00 + v01.x * wt01 + v10.x * wt10 + v11.x * wt11;
            e1[q] = v00.y * wt00 + v01.y * wt01 + v10.y * wt10 + v11.y * wt11;
        }
        actp[(2 * l)     * TPB] = make_float2(e0[0], e0[1]);
        actp[(2 * l + 1) * TPB] = make_float2(e1[0], e1[1]);
    }

    // ---------------- layer 0: enc(32) @ W0(32x64), relu ----------------
    // h[q][j] packs (out_{2j}, out_{2j+1}) of point q
    unsigned long long h1[PPT][HID / 2];
#pragma unroll
    for (int j = 0; j < HID / 2; ++j) { h1[0][j] = 0ull; h1[1][j] = 0ull; }

#pragma unroll 4
    for (int k = 0; k < ENC_DIM; ++k) {
        const float2 a = actp[k * TPB];
        const unsigned long long b0 = pack2(a.x, a.x);
        const unsigned long long b1 = pack2(a.y, a.y);
        const ulonglong2* wr = (const ulonglong2*)(sW0 + k * HID);
#pragma unroll
        for (int j = 0; j < HID / 4; ++j) {
            const ulonglong2 w = wr[j];
            h1[0][2 * j]     = fma2(b0, w.x, h1[0][2 * j]);
            h1[0][2 * j + 1] = fma2(b0, w.y, h1[0][2 * j + 1]);
            h1[1][2 * j]     = fma2(b1, w.x, h1[1][2 * j]);
            h1[1][2 * j + 1] = fma2(b1, w.y, h1[1][2 * j + 1]);
        }
    }
    // relu -> act pair columns (no sync needed: own column only)
#pragma unroll
    for (int j = 0; j < HID / 2; ++j) {
        float a0, a1, b0, b1;
        unpack2(h1[0][j], a0, a1);
        unpack2(h1[1][j], b0, b1);
        actp[(2 * j)     * TPB] = make_float2(fmaxf(a0, 0.f), fmaxf(b0, 0.f));
        actp[(2 * j + 1) * TPB] = make_float2(fmaxf(a1, 0.f), fmaxf(b1, 0.f));
    }

    // ---------------- layer 1: h(64) @ W1(64x64) ----------------
    unsigned long long h2[PPT][HID / 2];
#pragma unroll
    for (int j = 0; j < HID / 2; ++j) { h2[0][j] = 0ull; h2[1][j] = 0ull; }

#pragma unroll 4
    for (int k = 0; k < HID; ++k) {
        const float2 a = actp[k * TPB];
        const unsigned long long b0 = pack2(a.x, a.x);
        const unsigned long long b1 = pack2(a.y, a.y);
        const ulonglong2* wr = (const ulonglong2*)(sW1 + k * HID);
#pragma unroll
        for (int j = 0; j < HID / 4; ++j) {
            const ulonglong2 w = wr[j];
            h2[0][2 * j]     = fma2(b0, w.x, h2[0][2 * j]);
            h2[0][2 * j + 1] = fma2(b0, w.y, h2[0][2 * j + 1]);
            h2[1][2 * j]     = fma2(b1, w.x, h2[1][2 * j]);
            h2[1][2 * j + 1] = fma2(b1, w.y, h2[1][2 * j + 1]);
        }
    }

    // ---------------- layer 2: relu(h2)(64) @ W2(64x3) ----------------
    float o[PPT][OUTC] = {{0.f, 0.f, 0.f}, {0.f, 0.f, 0.f}};
    const float2* w2p = (const float2*)sW2;
#pragma unroll
    for (int j = 0; j < HID / 2; ++j) {
        // weights for outputs 2j, 2j+1: 6 floats
        const float2 wA = w2p[3 * j];        // w[2j][0], w[2j][1]
        const float2 wB = w2p[3 * j + 1];    // w[2j][2], w[2j+1][0]
        const float2 wC = w2p[3 * j + 2];    // w[2j+1][1], w[2j+1][2]
        float a0, a1, b0, b1;
        unpack2(h2[0][j], a0, a1);
        unpack2(h2[1][j], b0, b1);
        a0 = fmaxf(a0, 0.f); a1 = fmaxf(a1, 0.f);
        b0 = fmaxf(b0, 0.f); b1 = fmaxf(b1, 0.f);
        o[0][0] += a0 * wA.x + a1 * wB.y;
        o[0][1] += a0 * wA.y + a1 * wC.x;
        o[0][2] += a0 * wB.x + a1 * wC.y;
        o[1][0] += b0 * wA.x + b1 * wB.y;
        o[1][1] += b0 * wA.y + b1 * wC.x;
        o[1][2] += b0 * wB.x + b1 * wC.y;
    }

#pragma unroll
    for (int c = 0; c < OUTC; ++c)
        ((float2*)(out + (size_t)c * NPTS))[t] = make_float2(o[0][c], o[1][c]);
}

extern "C" void kernel_launch(void* const* d_in, const int* in_sizes, int n_in,
                              void* d_out, int out_size)
{
    const float* xy  = nullptr;
    const float* tab = nullptr;
    const float* W0  = nullptr;
    const float* W1  = nullptr;
    const float* W2  = nullptr;

    for (int i = 0; i < n_in; ++i) {
        switch (in_sizes[i]) {
            case 2 * NPTS:              xy  = (const float*)d_in[i]; break; // 2097152
            case (int)(NLEV * TBL * 2): tab = (const float*)d_in[i]; break; // 16777216
            case ENC_DIM * HID:         W0  = (const float*)d_in[i]; break; // 2048
            case HID * HID:             W1  = (const float*)d_in[i]; break; // 4096
            case HID * OUTC:            W2  = (const float*)d_in[i]; break; // 192
            default: break;
        }
    }

    cudaFuncSetAttribute(ngp_fused_kernel,
                         cudaFuncAttributeMaxDynamicSharedMemorySize, SMEM_BYTES);

    ngp_fused_kernel<<<NPTS / (TPB * PPT), TPB, SMEM_BYTES>>>(
        xy, tab, W0, W1, W2, (float*)d_out);
}

// round 10
// speedup vs baseline: 1.6960x; 1.0702x over previous
#include <cuda_runtime.h>
#include <cstdint>

#define S_GRID   1024
#define NPTS     (S_GRID * S_GRID)
#define NLEV     16
#define TBL      (1u << 19)
#define TMASK    (TBL - 1u)
#define ENC_DIM  32
#define HID      64
#define OUTC     3
#define PRIME_Y  2654435761u
#define TPB      128
#define WROW     72              // padded weight row: [32 | pad4 | 32 | pad4] floats

__device__ __constant__ int c_res[NLEV] =
    {16, 24, 36, 54, 81, 121, 182, 273, 410, 615,
     922, 1383, 2075, 3113, 4670, 7006};
// levels 0..9 dense ((res+1)^2 <= 2^19), 10..15 hashed

// ---------------- f32x2 packed math helpers ----------------
__device__ __forceinline__ unsigned long long pack2(float x, float y) {
    unsigned long long r;
    asm("mov.b64 %0, {%1, %2};" : "=l"(r) : "f"(x), "f"(y));
    return r;
}
__device__ __forceinline__ void unpack2(unsigned long long v, float& x, float& y) {
    asm("mov.b64 {%0, %1}, %2;" : "=f"(x), "=f"(y) : "l"(v));
}
__device__ __forceinline__ unsigned long long fma2(unsigned long long a,
                                                   unsigned long long b,
                                                   unsigned long long c) {
    unsigned long long d;
    asm("fma.rn.f32x2 %0, %1, %2, %3;" : "=l"(d) : "l"(a), "l"(b), "l"(c));
    return d;
}

// smem (floats): W0p[32*72] | W1p[64*72] | W2[192] | act4 float4[64][64]
#define SM_W0   0
#define SM_W1   (32 * WROW)                       // 2304
#define SM_W2   (SM_W1 + 64 * WROW)               // 6912
#define SM_ACT  (SM_W2 + 192)                     // 7104 (16B aligned: 7104*4=28416 ✓)
#define SMEM_FLOATS (SM_ACT + HID * (TPB / 2) * 4)
#define SMEM_BYTES  (SMEM_FLOATS * 4)

__global__ __launch_bounds__(TPB, 2)
void ngp_fused_kernel(const float* __restrict__ xy,
                      const float* __restrict__ tables,
                      const float* __restrict__ gW0,
                      const float* __restrict__ gW1,
                      const float* __restrict__ gW2,
                      float* __restrict__ out)
{
    extern __shared__ float smem[];
    float*  sW0p = smem + SM_W0;
    float*  sW1p = smem + SM_W1;
    float*  sW2  = smem + SM_W2;
    float4* act4 = (float4*)(smem + SM_ACT);      // [k][64] slots; warp region = cols warp*16..+15

    const int tid  = threadIdx.x;
    const int lane = tid & 31;
    const int warp = tid >> 5;
    const int pair = lane >> 1;
    const int half = lane & 1;

    // ---- stage weights: padded halves so even/odd lane LDS hit distinct banks ----
    for (int f = tid; f < (ENC_DIM * HID) / 4; f += TPB) {      // 512 float4
        const int k = f >> 4, i = f & 15, h = i >> 3, j4 = i & 7;
        ((float4*)sW0p)[k * (WROW / 4) + h * 9 + j4] = ((const float4*)gW0)[f];
    }
    for (int f = tid; f < (HID * HID) / 4; f += TPB) {          // 1024 float4
        const int k = f >> 4, i = f & 15, h = i >> 3, j4 = i & 7;
        ((float4*)sW1p)[k * (WROW / 4) + h * 9 + j4] = ((const float4*)gW1)[f];
    }
    if (tid < HID * OUTC / 2)
        ((float2*)sW2)[tid] = ((const float2*)gW2)[tid];
    __syncthreads();

    const int t = blockIdx.x * TPB + tid;         // this lane's point-pair index
    const float4 xyv = ((const float4*)xy)[t];    // points 2t, 2t+1
    const float px[2] = {xyv.x, xyv.z};
    const float py[2] = {xyv.y, xyv.w};

    // encode store view: float2 slots; slot(k) = k*128 + warp*32 + lane
    float2* acts = ((float2*)act4) + warp * 32 + lane;

    // ---------------- hash-grid encoding (2 points per lane) ----------------
#pragma unroll
    for (int l = 0; l < NLEV; ++l) {
        const int   res  = c_res[l];
        const float resf = (float)res;
        const float2* tab = (const float2*)(tables) + (size_t)l * TBL;
        float e0[2], e1[2];
#pragma unroll
        for (int q = 0; q < 2; ++q) {
            const float pos0 = px[q] * resf;
            const float pos1 = py[q] * resf;
            const float f0 = floorf(pos0);
            const float f1 = floorf(pos1);
            const int   i0 = (int)f0;
            const int   i1 = (int)f1;
            const float w0 = pos0 - f0;
            const float w1 = pos1 - f1;

            int idx00, idx01, idx10, idx11;
            if (l < 10) {
                const int r1   = res + 1;
                const int base = i0 + i1 * r1;
                idx00 = base;
                idx01 = base + r1;
                idx10 = base + 1;
                idx11 = base + r1 + 1;
            } else {
                const unsigned u0 = (unsigned)i0;
                const unsigned u1 = (unsigned)i1;
                const unsigned h0 = u1 * PRIME_Y;
                const unsigned h1 = (u1 + 1u) * PRIME_Y;
                idx00 = (int)((u0        ^ h0) & TMASK);
                idx01 = (int)((u0        ^ h1) & TMASK);
                idx10 = (int)(((u0 + 1u) ^ h0) & TMASK);
                idx11 = (int)(((u0 + 1u) ^ h1) & TMASK);
            }

            const float2 v00 = __ldg(tab + idx00);
            const float2 v01 = __ldg(tab + idx01);
            const float2 v10 = __ldg(tab + idx10);
            const float2 v11 = __ldg(tab + idx11);

            const float a0 = 1.f - w0;
            const float a1 = 1.f - w1;
            const float wt00 = a0 * a1;
            const float wt01 = a0 * w1;
            const float wt10 = w0 * a1;
            const float wt11 = w0 * w1;

            e0[q] = v00.x * wt00 + v01.x * wt01 + v10.x * wt10 + v11.x * wt11;
            e1[q] = v00.y * wt00 + v01.y * wt01 + v10.y * wt10 + v11.y * wt11;
        }
        acts[(2 * l)     * 128] = make_float2(e0[0], e0[1]);
        acts[(2 * l + 1) * 128] = make_float2(e1[0], e1[1]);
    }
    __syncwarp();

    const float4* actr = act4 + warp * 16 + pair;          // read view (both pair-lanes same addr)
    const int     hoff = half * 36;                        // padded half offset in floats

    // ---------------- layer 0: enc(32) @ W0-half(32x32), 4 points ----------------
    unsigned long long acc[4][16];
#pragma unroll
    for (int q = 0; q < 4; ++q)
#pragma unroll
        for (int m = 0; m < 16; ++m) acc[q][m] = 0ull;

#pragma unroll 4
    for (int k = 0; k < ENC_DIM; ++k) {
        const float4 av = actr[k * 64];
        const unsigned long long b0 = pack2(av.x, av.x);
        const unsigned long long b1 = pack2(av.y, av.y);
        const unsigned long long b2 = pack2(av.z, av.z);
        const unsigned long long b3 = pack2(av.w, av.w);
        const ulonglong2* wr = (const ulonglong2*)(sW0p + k * WROW + hoff);
#pragma unroll
        for (int j = 0; j < 8; ++j) {
            const ulonglong2 w = wr[j];
            acc[0][2 * j]     = fma2(b0, w.x, acc[0][2 * j]);
            acc[0][2 * j + 1] = fma2(b0, w.y, acc[0][2 * j + 1]);
            acc[1][2 * j]     = fma2(b1, w.x, acc[1][2 * j]);
            acc[1][2 * j + 1] = fma2(b1, w.y, acc[1][2 * j + 1]);
            acc[2][2 * j]     = fma2(b2, w.x, acc[2][2 * j]);
            acc[2][2 * j + 1] = fma2(b2, w.y, acc[2][2 * j + 1]);
            acc[3][2 * j]     = fma2(b3, w.x, acc[3][2 * j]);
            acc[3][2 * j + 1] = fma2(b3, w.y, acc[3][2 * j + 1]);
        }
    }
    __syncwarp();

    // relu -> store h1: lane owns features half*32+2m, +2m+1 for all 4 points
    {
        float4* wrt = act4 + warp * 16 + pair;
#pragma unroll
        for (int m = 0; m < 16; ++m) {
            float x0, y0, x1, y1, x2, y2, x3, y3;
            unpack2(acc[0][m], x0, y0);
            unpack2(acc[1][m], x1, y1);
            unpack2(acc[2][m], x2, y2);
            unpack2(acc[3][m], x3, y3);
            const int f0 = half * 32 + 2 * m;
            wrt[f0 * 64] = make_float4(fmaxf(x0, 0.f), fmaxf(x1, 0.f),
                                       fmaxf(x2, 0.f), fmaxf(x3, 0.f));
            wrt[(f0 + 1) * 64] = make_float4(fmaxf(y0, 0.f), fmaxf(y1, 0.f),
                                             fmaxf(y2, 0.f), fmaxf(y3, 0.f));
        }
    }
    __syncwarp();

    // ---------------- layer 1: h1(64) @ W1-half(64x32), 4 points ----------------
    unsigned long long acc2[4][16];
#pragma unroll
    for (int q = 0; q < 4; ++q)
#pragma unroll
        for (int m = 0; m < 16; ++m) acc2[q][m] = 0ull;

#pragma unroll 4
    for (int k = 0; k < HID; ++k) {
        const float4 av = actr[k * 64];
        const unsigned long long b0 = pack2(av.x, av.x);
        const unsigned long long b1 = pack2(av.y, av.y);
        const unsigned long long b2 = pack2(av.z, av.z);
        const unsigned long long b3 = pack2(av.w, av.w);
        const ulonglong2* wr = (const ulonglong2*)(sW1p + k * WROW + hoff);
#pragma unroll
        for (int j = 0; j < 8; ++j) {
            const ulonglong2 w = wr[j];
            acc2[0][2 * j]     = fma2(b0, w.x, acc2[0][2 * j]);
            acc2[0][2 * j + 1] = fma2(b0, w.y, acc2[0][2 * j + 1]);
            acc2[1][2 * j]     = fma2(b1, w.x, acc2[1][2 * j]);
            acc2[1][2 * j + 1] = fma2(b1, w.y, acc2[1][2 * j + 1]);
            acc2[2][2 * j]     = fma2(b2, w.x, acc2[2][2 * j]);
            acc2[2][2 * j + 1] = fma2(b2, w.y, acc2[2][2 * j + 1]);
            acc2[3][2 * j]     = fma2(b3, w.x, acc2[3][2 * j]);
            acc2[3][2 * j + 1] = fma2(b3, w.y, acc2[3][2 * j + 1]);
        }
    }

    // ---------------- layer 2: relu(h2) @ W2(64x3), partial over own features ----------------
    float o[4][OUTC] = {{0.f,0.f,0.f},{0.f,0.f,0.f},{0.f,0.f,0.f},{0.f,0.f,0.f}};
    const float2* w2p = (const float2*)sW2;
#pragma unroll
    for (int m = 0; m < 16; ++m) {
        const int f0 = half * 32 + 2 * m;          // even
        const int bidx = (f0 * 3) >> 1;            // float2 index
        const float2 wA = w2p[bidx];               // w[f0][0], w[f0][1]
        const float2 wB = w2p[bidx + 1];           // w[f0][2], w[f0+1][0]
        const float2 wC = w2p[bidx + 2];           // w[f0+1][1], w[f0+1][2]
#pragma unroll
        for (int q = 0; q < 4; ++q) {
            float a, b;
            unpack2(acc2[q][m], a, b);
            a = fmaxf(a, 0.f);
            b = fmaxf(b, 0.f);
            o[q][0] += a * wA.x + b * wB.y;
            o[q][1] += a * wA.y + b * wC.x;
            o[q][2] += a * wB.x + b * wC.y;
        }
    }
    // combine halves within lane pair
#pragma unroll
    for (int q = 0; q < 4; ++q)
#pragma unroll
        for (int c = 0; c < OUTC; ++c)
            o[q][c] += __shfl_xor_sync(0xffffffffu, o[q][c], 1);

    // even lane writes points 4i,4i+1 ; odd lane writes 4i+2,4i+3 -> float2 index == t
    const int qb = 2 * half;
#pragma unroll
    for (int c = 0; c < OUTC; ++c)
        ((float2*)(out + (size_t)c * NPTS))[t] = make_float2(o[qb][c], o[qb + 1][c]);
}

extern "C" void kernel_launch(void* const* d_in, const int* in_sizes, int n_in,
                              void* d_out, int out_size)
{
    const float* xy  = nullptr;
    const float* tab = nullptr;
    const float* W0  = nullptr;
    const float* W1  = nullptr;
    const float* W2  = nullptr;

    for (int i = 0; i < n_in; ++i) {
        switch (in_sizes[i]) {
            case 2 * NPTS:              xy  = (const float*)d_in[i]; break; // 2097152
            case (int)(NLEV * TBL * 2): tab = (const float*)d_in[i]; break; // 16777216
            case ENC_DIM * HID:         W0  = (const float*)d_in[i]; break; // 2048
            case HID * HID:             W1  = (const float*)d_in[i]; break; // 4096
            case HID * OUTC:            W2  = (const float*)d_in[i]; break; // 192
            default: break;
        }
    }

    cudaFuncSetAttribute(ngp_fused_kernel,
                         cudaFuncAttributeMaxDynamicSharedMemorySize, SMEM_BYTES);

    // 256 points per block (4 warps x 64), 4096 blocks
    ngp_fused_kernel<<<NPTS / (TPB * 2), TPB, SMEM_BYTES>>>(
        xy, tab, W0, W1, W2, (float*)d_out);
}